// round 1
// baseline (speedup 1.0000x reference)
#include <cuda_runtime.h>

#define FULL 0xFFFFFFFFu

// Per-batch partial results (loss_b + kld_b). Static device scratch (no allocs).
__device__ float g_partials[4096];

__device__ __forceinline__ float sel4(float e0, float e1, float e2, float e3, int x) {
    float lo = (x & 1) ? e1 : e0;
    float hi = (x & 1) ? e3 : e2;
    return (x & 2) ? hi : lo;
}

// One warp per batch element. Lane L owns states k0=2L, k1=2L+1 (k in 0..63);
// state 64 is carried redundantly on all lanes (only lane 31's copy is valid,
// since it uses lane-local prev[63]). Linear-space scaled forward algorithm.
__global__ void __launch_bounds__(128)
phmm_kernel(const int* __restrict__ xin,       // (B,128) int32 in [0,4)
            const float* __restrict__ trans,   // (B,65,7)
            const float* __restrict__ emis,    // (B,64,4)
            const float* __restrict__ mus,     // (B,16)
            const float* __restrict__ logvars) // (B,16)
{
    const int lane = threadIdx.x & 31;
    const int warp = threadIdx.x >> 5;
    const int b = blockIdx.x * 4 + warp;

    __shared__ int sx[4][128];
    {
        const int* xb = xin + b * 128;
        #pragma unroll
        for (int i = 0; i < 4; i++) sx[warp][lane + 32 * i] = xb[lane + 32 * i];
    }

    // ---- load + exp transitions (order: M2M, M2I, M2D, I2M, I2I, D2M, D2D) ----
    const float* ab = trans + b * 455;          // 65*7
    const float* a0 = ab + (2 * lane) * 7;
    float tM2M0  = __expf(a0[0]);
    float tqM2I0 = 0.25f * __expf(a0[1]);       // LOG_Q folded in
    float tM2D0  = __expf(a0[2]);
    float tI2M0  = __expf(a0[3]);
    float tqI2I0 = 0.25f * __expf(a0[4]);
    float tD2M0  = __expf(a0[5]);
    float tD2D0  = __expf(a0[6]);
    float tM2M1  = __expf(a0[7]);
    float tqM2I1 = 0.25f * __expf(a0[8]);
    float tM2D1  = __expf(a0[9]);
    float tI2M1  = __expf(a0[10]);
    float tqI2I1 = 0.25f * __expf(a0[11]);
    float tD2M1  = __expf(a0[12]);
    float tD2D1  = __expf(a0[13]);
    // state 64 transitions (broadcast load; valid data identical on all lanes)
    const float* a64 = ab + 64 * 7;
    float t64M2M  = __expf(a64[0]);
    float tq64M2I = 0.25f * __expf(a64[1]);
    float t64I2M  = __expf(a64[3]);
    float tq64I2I = 0.25f * __expf(a64[4]);
    float t64D2M  = __expf(a64[5]);

    // ---- load + exp emissions ----
    // FM_new[k0] needs Em[2L-1] (row A), FM_new[k1] needs Em[2L] (row B),
    // FM_new[64] needs Em[63] (row C, only lane 31's result is used).
    const float* eb = emis + b * 256;           // 64*4
    const int rA = (lane == 0) ? 0 : (2 * lane - 1);
    float eA0 = __expf(eb[rA * 4 + 0]), eA1 = __expf(eb[rA * 4 + 1]);
    float eA2 = __expf(eb[rA * 4 + 2]), eA3 = __expf(eb[rA * 4 + 3]);
    const int rB = 2 * lane;
    float eB0 = __expf(eb[rB * 4 + 0]), eB1 = __expf(eb[rB * 4 + 1]);
    float eB2 = __expf(eb[rB * 4 + 2]), eB3 = __expf(eb[rB * 4 + 3]);
    float eC0 = __expf(eb[63 * 4 + 0]), eC1 = __expf(eb[63 * 4 + 1]);
    float eC2 = __expf(eb[63 * 4 + 2]), eC3 = __expf(eb[63 * 4 + 3]);

    // ---- init linear-space states ----
    float FM0 = (lane == 0) ? 1.0f : 0.0f;      // exp(0) at k=0, exp(NEG)->0 else
    float FM1 = 0.0f;
    float FI0 = 0.0f, FI1 = 0.0f;
    float FM64 = 0.0f, FI64 = 0.0f;
    float FD0, FD1, fdTop;                      // fdTop = FD[2L+2] (lane31 -> FD[64])
    float S = 0.0f;                             // accumulated log-scale

    // D-chain as an affine scan: g[k] = b[k] + c[k]*g[k-1], g[0]=0,
    // b[k] = T_M2D[k-1]*FM[k-1], c[k] = T_D2D[k-1].
    // Lane L composes steps (2L+1, 2L+2); inclusive warp scan gives g[2L+2].
#define DCHAIN()                                                              \
    {                                                                         \
        float bA = tM2D0 * FM0;     /* step 2L+1 */                           \
        float bB = tM2D1 * FM1;     /* step 2L+2 */                           \
        float Bc = fmaf(tD2D1, bA, bB);                                       \
        float Cc = tD2D1 * tD2D0;                                             \
        _Pragma("unroll")                                                     \
        for (int off = 1; off < 32; off <<= 1) {                              \
            float Bp = __shfl_up_sync(FULL, Bc, off);                         \
            float Cp = __shfl_up_sync(FULL, Cc, off);                         \
            if (lane >= off) { Bc = fmaf(Cc, Bp, Bc); Cc = Cc * Cp; }         \
        }                                                                     \
        float fdPrev = __shfl_up_sync(FULL, Bc, 1);                           \
        FD0 = (lane == 0) ? 0.0f : fdPrev;                                    \
        FD1 = fmaf(tD2D0, FD0, bA);                                           \
        fdTop = Bc;                                                           \
    }

#define STEP(l)                                                               \
    {                                                                         \
        int x = sx[warp][(l)];                                                \
        float eA = sel4(eA0, eA1, eA2, eA3, x);                               \
        float eB = sel4(eB0, eB1, eB2, eB3, x);                               \
        float eC = sel4(eC0, eC1, eC2, eC3, x);                               \
        float p0 = fmaf(tD2M0, FD0, fmaf(tI2M0, FI0, tM2M0 * FM0));           \
        float p1 = fmaf(tD2M1, FD1, fmaf(tI2M1, FI1, tM2M1 * FM1));           \
        float pUp = __shfl_up_sync(FULL, p1, 1);                              \
        FI0 = fmaf(tqI2I0, FI0, tqM2I0 * FM0);   /* uses OLD FM */            \
        FI1 = fmaf(tqI2I1, FI1, tqM2I1 * FM1);                                \
        FI64 = fmaf(tq64I2I, FI64, tq64M2I * FM64);                           \
        FM0 = (lane == 0) ? 0.0f : eA * pUp;                                  \
        FM1 = eB * p0;                                                        \
        FM64 = eC * p1;            /* valid on lane 31 only */                \
        DCHAIN();                                                             \
    }

    DCHAIN();  // fD0 from initial fM0

    #pragma unroll 1
    for (int lq = 0; lq < 32; lq++) {
        STEP(4 * lq + 0);
        STEP(4 * lq + 1);
        STEP(4 * lq + 2);
        STEP(4 * lq + 3);
        // rescale: divide all states by warp max, accumulate log
        float m = fmaxf(fmaxf(FM0, FM1), fmaxf(FI0, FI1));
        m = fmaxf(m, fmaxf(fmaxf(FD0, FD1), fdTop));
        m = fmaxf(m, fmaxf(FM64, FI64));
        #pragma unroll
        for (int off = 16; off; off >>= 1)
            m = fmaxf(m, __shfl_xor_sync(FULL, m, off));
        m = fmaxf(m, 1e-30f);
        float r = 1.0f / m;
        S += __logf(m);
        FM0 *= r; FM1 *= r; FI0 *= r; FI1 *= r;
        FD0 *= r; FD1 *= r; fdTop *= r;
        FM64 *= r; FI64 *= r;
    }

    // ---- final: -logsumexp over the three end transitions (lane 31 holds k=64) ----
    float P = fmaf(t64D2M, fdTop, fmaf(t64I2M, FI64, t64M2M * FM64));
    float loss = -(S + __logf(P));              // valid on lane 31

    // ---- KLD: lanes 0..15 each handle one latent dim ----
    float kt = 0.0f;
    if (lane < 16) {
        float mu = mus[b * 16 + lane];
        float lv = logvars[b * 16 + lane];
        kt = 1.0f + lv - mu * mu - __expf(lv);
    }
    #pragma unroll
    for (int off = 16; off; off >>= 1)
        kt += __shfl_xor_sync(FULL, kt, off);
    float kld = -0.5f * kt;

    if (lane == 31) g_partials[b] = loss + kld;
#undef STEP
#undef DCHAIN
}

__global__ void reduce_kernel(float* __restrict__ out, int B) {
    __shared__ float sm[256];
    float s = 0.0f;
    for (int i = threadIdx.x; i < B; i += 256) s += g_partials[i];
    sm[threadIdx.x] = s;
    __syncthreads();
    #pragma unroll
    for (int st = 128; st; st >>= 1) {
        if (threadIdx.x < st) sm[threadIdx.x] += sm[threadIdx.x + st];
        __syncthreads();
    }
    if (threadIdx.x == 0) out[0] = sm[0] * (1.0f / (float)B);
}

extern "C" void kernel_launch(void* const* d_in, const int* in_sizes, int n_in,
                              void* d_out, int out_size) {
    const int*   x  = (const int*)d_in[0];    // batch_input (B,128)
    const float* a  = (const float*)d_in[1];  // transition_probs (B,65,7)
    const float* e  = (const float*)d_in[2];  // emission_probs (B,64,4)
    const float* mu = (const float*)d_in[3];  // mus (B,16)
    const float* lv = (const float*)d_in[4];  // logvars (B,16)
    const int B = in_sizes[0] / 128;          // 4096
    phmm_kernel<<<B / 4, 128>>>(x, a, e, mu, lv);
    reduce_kernel<<<1, 256>>>((float*)d_out, B);
}

// round 2
// speedup vs baseline: 1.0921x; 1.0921x over previous
#include <cuda_runtime.h>

#define FULL 0xFFFFFFFFu

// Per-block partial results + completion counter (static device scratch).
__device__ float g_partials[1024];
__device__ unsigned int g_cnt = 0;

__device__ __forceinline__ float sel4(float e0, float e1, float e2, float e3, int x) {
    float lo = (x & 1) ? e1 : e0;
    float hi = (x & 1) ? e3 : e2;
    return (x & 2) ? hi : lo;
}

// One warp per batch element. Lane L owns states k0=2L, k1=2L+1 (k in 0..63);
// state 64 carried redundantly (lane 31's copy valid). Linear-space scaled
// forward. D-chain uses constant prefix-products: fD[k] = P[k] * prefixsum(b/P).
__global__ void __launch_bounds__(128)
phmm_kernel(const int* __restrict__ xin,       // (B,128) int32 in [0,4)
            const float* __restrict__ trans,   // (B,65,7)
            const float* __restrict__ emis,    // (B,64,4)
            const float* __restrict__ mus,     // (B,16)
            const float* __restrict__ logvars, // (B,16)
            float* __restrict__ out)           // scalar
{
    const int lane = threadIdx.x & 31;
    const int warp = threadIdx.x >> 5;
    const int b = blockIdx.x * 4 + warp;

    __shared__ int sx[4][128];
    __shared__ float sred[4];
    __shared__ int sflag;
    __shared__ float s2[128];
    {
        const int* xb = xin + b * 128;
        #pragma unroll
        for (int i = 0; i < 4; i++) sx[warp][lane + 32 * i] = xb[lane + 32 * i];
    }

    // ---- load + exp transitions (order: M2M, M2I, M2D, I2M, I2I, D2M, D2D) ----
    const float* ab = trans + b * 455;          // 65*7
    const float* a0 = ab + (2 * lane) * 7;
    float tM2M0  = __expf(a0[0]);
    float tqM2I0 = 0.25f * __expf(a0[1]);       // LOG_Q folded in
    float tM2D0  = __expf(a0[2]);
    float tI2M0  = __expf(a0[3]);
    float tqI2I0 = 0.25f * __expf(a0[4]);
    float tD2M0  = __expf(a0[5]);
    float tD2D0  = __expf(a0[6]);
    float tM2M1  = __expf(a0[7]);
    float tqM2I1 = 0.25f * __expf(a0[8]);
    float tM2D1  = __expf(a0[9]);
    float tI2M1  = __expf(a0[10]);
    float tqI2I1 = 0.25f * __expf(a0[11]);
    float tD2M1  = __expf(a0[12]);
    float tD2D1  = __expf(a0[13]);
    const float* a64 = ab + 64 * 7;
    float t64M2M  = __expf(a64[0]);
    float tq64M2I = 0.25f * __expf(a64[1]);
    float t64I2M  = __expf(a64[3]);
    float tq64I2I = 0.25f * __expf(a64[4]);
    float t64D2M  = __expf(a64[5]);

    // ---- load + exp emissions ----
    const float* eb = emis + b * 256;           // 64*4
    const int rA = (lane == 0) ? 0 : (2 * lane - 1);
    float eA0 = __expf(eb[rA * 4 + 0]), eA1 = __expf(eb[rA * 4 + 1]);
    float eA2 = __expf(eb[rA * 4 + 2]), eA3 = __expf(eb[rA * 4 + 3]);
    const int rB = 2 * lane;
    float eB0 = __expf(eb[rB * 4 + 0]), eB1 = __expf(eb[rB * 4 + 1]);
    float eB2 = __expf(eb[rB * 4 + 2]), eB3 = __expf(eb[rB * 4 + 3]);
    float eC0 = __expf(eb[63 * 4 + 0]), eC1 = __expf(eb[63 * 4 + 1]);
    float eC2 = __expf(eb[63 * 4 + 2]), eC3 = __expf(eb[63 * 4 + 3]);

    // ---- precompute D-chain prefix products (constant over timesteps) ----
    // c[k] = tD2D[k-1], P[k] = prod_{i<=k} c[i], P[0]=1.
    // Lane L owns c at chain indices 2L+1 (tD2D0) and 2L+2 (tD2D1).
    float P2L, P_A, P_B, cA, cB;
    {
        float Q = tD2D0 * tD2D1;                // pair product
        #pragma unroll
        for (int off = 1; off < 32; off <<= 1) {
            float q = __shfl_up_sync(FULL, Q, off);
            if (lane >= off) Q *= q;
        }
        float Qex = __shfl_up_sync(FULL, Q, 1);
        if (lane == 0) Qex = 1.0f;
        P2L = Qex;                              // P[2L]
        P_A = Qex * tD2D0;                      // P[2L+1]
        P_B = Q;                                // P[2L+2]
        cA = __fdividef(tM2D0, P_A);            // b[2L+1]/P[2L+1] per unit FM0
        cB = __fdividef(tM2D1, P_B);
    }

    // ---- init linear-space states ----
    float FM0 = (lane == 0) ? 1.0f : 0.0f;
    float FM1 = 0.0f;
    float FI0 = 0.0f, FI1 = 0.0f;
    float FM64 = 0.0f, FI64 = 0.0f;
    float FD0, FD1, fdTop;
    float S = 0.0f;

    // fD[k] = P[k] * sum_{j<=k} u[j], u[j] = b[j]/P[j], b[j]=tM2D[j-1]*FM[j-1].
#define DCHAIN()                                                              \
    {                                                                         \
        float uA = cA * FM0;                                                  \
        float uB = cB * FM1;                                                  \
        float pr = uA + uB;                                                   \
        float T = pr;                                                         \
        _Pragma("unroll")                                                     \
        for (int off = 1; off < 32; off <<= 1) {                              \
            float t = __shfl_up_sync(FULL, T, off);                           \
            if (lane >= off) T += t;                                          \
        }                                                                     \
        float excl = T - pr;                                                  \
        FD0 = P2L * excl;                                                     \
        FD1 = P_A * (excl + uA);                                              \
        fdTop = P_B * T;                                                      \
    }

#define STEP(l)                                                               \
    {                                                                         \
        int x = sx[warp][(l)];                                                \
        float eA = sel4(eA0, eA1, eA2, eA3, x);                               \
        float eB = sel4(eB0, eB1, eB2, eB3, x);                               \
        float eC = sel4(eC0, eC1, eC2, eC3, x);                               \
        float p0 = fmaf(tD2M0, FD0, fmaf(tI2M0, FI0, tM2M0 * FM0));           \
        float p1 = fmaf(tD2M1, FD1, fmaf(tI2M1, FI1, tM2M1 * FM1));           \
        float pUp = __shfl_up_sync(FULL, p1, 1);                              \
        FI0 = fmaf(tqI2I0, FI0, tqM2I0 * FM0);   /* uses OLD FM */            \
        FI1 = fmaf(tqI2I1, FI1, tqM2I1 * FM1);                                \
        FI64 = fmaf(tq64I2I, FI64, tq64M2I * FM64);                           \
        FM0 = (lane == 0) ? 0.0f : eA * pUp;                                  \
        FM1 = eB * p0;                                                        \
        FM64 = eC * p1;            /* valid on lane 31 only */                \
        DCHAIN();                                                             \
    }

    DCHAIN();  // fD0 from initial fM0

    #pragma unroll 1
    for (int lq = 0; lq < 16; lq++) {
        STEP(8 * lq + 0);
        STEP(8 * lq + 1);
        STEP(8 * lq + 2);
        STEP(8 * lq + 3);
        STEP(8 * lq + 4);
        STEP(8 * lq + 5);
        STEP(8 * lq + 6);
        STEP(8 * lq + 7);
        // rescale: divide all states by warp max, accumulate log
        float m = fmaxf(fmaxf(FM0, FM1), fmaxf(FI0, FI1));
        m = fmaxf(m, fmaxf(fmaxf(FD0, FD1), fdTop));
        m = fmaxf(m, fmaxf(FM64, FI64));
        #pragma unroll
        for (int off = 16; off; off >>= 1)
            m = fmaxf(m, __shfl_xor_sync(FULL, m, off));
        m = fmaxf(m, 1e-30f);
        float r = 1.0f / m;
        S += __logf(m);
        FM0 *= r; FM1 *= r; FI0 *= r; FI1 *= r;
        FD0 *= r; FD1 *= r; fdTop *= r;
        FM64 *= r; FI64 *= r;
    }

    // ---- final: -log of the three end transitions (lane 31 holds k=64) ----
    float P = fmaf(t64D2M, fdTop, fmaf(t64I2M, FI64, t64M2M * FM64));
    float loss = -(S + __logf(P));              // valid on lane 31

    // ---- KLD: lanes 0..15 each handle one latent dim ----
    float kt = 0.0f;
    if (lane < 16) {
        float mu = mus[b * 16 + lane];
        float lv = logvars[b * 16 + lane];
        kt = 1.0f + lv - mu * mu - __expf(lv);
    }
    #pragma unroll
    for (int off = 16; off; off >>= 1)
        kt += __shfl_xor_sync(FULL, kt, off);
    float kld = -0.5f * kt;

    // ---- block-level partial, then last-block global reduction ----
    if (lane == 31) sred[warp] = loss + kld;
    __syncthreads();
    if (threadIdx.x == 0) {
        float v = (sred[0] + sred[1]) + (sred[2] + sred[3]);
        g_partials[blockIdx.x] = v;
        __threadfence();
        unsigned t = atomicAdd(&g_cnt, 1u);
        sflag = (t == gridDim.x - 1) ? 1 : 0;
    }
    __syncthreads();
    if (sflag) {
        // deterministic fixed-order reduction of 1024 block partials
        float s = 0.0f;
        #pragma unroll
        for (int i = 0; i < 8; i++)
            s += __ldcg(&g_partials[threadIdx.x + 128 * i]);
        s2[threadIdx.x] = s;
        __syncthreads();
        #pragma unroll
        for (int st = 64; st; st >>= 1) {
            if (threadIdx.x < st) s2[threadIdx.x] += s2[threadIdx.x + st];
            __syncthreads();
        }
        if (threadIdx.x == 0) {
            out[0] = s2[0] * (1.0f / 4096.0f);
            g_cnt = 0;  // self-reset for next launch (graph replay safe)
        }
    }
#undef STEP
#undef DCHAIN
}

extern "C" void kernel_launch(void* const* d_in, const int* in_sizes, int n_in,
                              void* d_out, int out_size) {
    const int*   x  = (const int*)d_in[0];    // batch_input (B,128)
    const float* a  = (const float*)d_in[1];  // transition_probs (B,65,7)
    const float* e  = (const float*)d_in[2];  // emission_probs (B,64,4)
    const float* mu = (const float*)d_in[3];  // mus (B,16)
    const float* lv = (const float*)d_in[4];  // logvars (B,16)
    const int B = in_sizes[0] / 128;          // 4096
    phmm_kernel<<<B / 4, 128>>>(x, a, e, mu, lv, (float*)d_out);
}

// round 3
// speedup vs baseline: 1.2331x; 1.1291x over previous
#include <cuda_runtime.h>

#define FULL 0xFFFFFFFFu

// Per-block partials + completion counter (static device scratch).
__device__ float g_partials[1024];
__device__ unsigned int g_cnt = 0;

// One warp per batch element. Lane L owns states k0=2L, k1=2L+1 (k in 0..63);
// state 64 carried redundantly (lane 31's copy valid). Linear-space scaled
// forward. D-chain via constant prefix products folded into consumers:
//   tD2M[2L]*fD[2L]   = dA * excl   (dA = tD2M0*P[2L])
//   tD2M[2L+1]*fD[2L+1] = dB * inclA (dB = tD2M1*P[2L+1])
// Emissions via warp-uniform shared LUT (x_l is the same for all lanes).
__global__ void __launch_bounds__(128)
phmm_kernel(const int* __restrict__ xin,       // (B,128) int32 in [0,4)
            const float* __restrict__ trans,   // (B,65,7)
            const float* __restrict__ emis,    // (B,64,4)
            const float* __restrict__ mus,     // (B,16)
            const float* __restrict__ logvars, // (B,16)
            float* __restrict__ out)           // scalar
{
    const int lane = threadIdx.x & 31;
    const int warp = threadIdx.x >> 5;
    const int b = blockIdx.x * 4 + warp;

    // sE layout: [0:512)=eA rows, [512:1024)=eB rows, [1024:1536)=eC rows.
    // Row index = warp*4 + x, 32 floats per row (per lane).
    __shared__ float sE[1536];
    __shared__ int   sx[4][128];
    __shared__ float sred[4];
    __shared__ int   sflag;
    __shared__ float s2[128];

    {
        const int* xb = xin + b * 128;
        #pragma unroll
        for (int i = 0; i < 4; i++) sx[warp][lane + 32 * i] = xb[lane + 32 * i];
    }

    // ---- load + exp transitions (order: M2M, M2I, M2D, I2M, I2I, D2M, D2D) ----
    const float* ab = trans + b * 455;          // 65*7
    const float* a0 = ab + (2 * lane) * 7;
    float tM2M0  = __expf(a0[0]);
    float tqM2I0 = 0.25f * __expf(a0[1]);       // LOG_Q folded in
    float tM2D0  = __expf(a0[2]);
    float tI2M0  = __expf(a0[3]);
    float tqI2I0 = 0.25f * __expf(a0[4]);
    float tD2M0  = __expf(a0[5]);
    float tD2D0  = __expf(a0[6]);
    float tM2M1  = __expf(a0[7]);
    float tqM2I1 = 0.25f * __expf(a0[8]);
    float tM2D1  = __expf(a0[9]);
    float tI2M1  = __expf(a0[10]);
    float tqI2I1 = 0.25f * __expf(a0[11]);
    float tD2M1  = __expf(a0[12]);
    float tD2D1  = __expf(a0[13]);
    const float* a64 = ab + 64 * 7;
    float t64M2M  = __expf(a64[0]);
    float tq64M2I = 0.25f * __expf(a64[1]);
    float t64I2M  = __expf(a64[3]);
    float tq64I2I = 0.25f * __expf(a64[4]);
    float t64D2M  = __expf(a64[5]);

    // ---- emission LUTs (per warp, per symbol, per lane) ----
    // FM_new[2L] needs Em[2L-1] (eA; lane0 entry forced to 0 so FM0 stays 0),
    // FM_new[2L+1] needs Em[2L] (eB), FM_new[64] needs Em[63] (eC, replicated).
    const float* eb = emis + b * 256;           // 64*4
    {
        const int rA = (lane == 0) ? 0 : (2 * lane - 1);
        const int rB = 2 * lane;
        #pragma unroll
        for (int x = 0; x < 4; x++) {
            int row = warp * 4 + x;
            sE[row * 32 + lane]        = (lane == 0) ? 0.0f : __expf(eb[rA * 4 + x]);
            sE[512 + row * 32 + lane]  = __expf(eb[rB * 4 + x]);
            sE[1024 + row * 32 + lane] = __expf(eb[63 * 4 + x]);
        }
    }
    __syncwarp();   // each warp only touches its own rows

    // ---- prefix products of tD2D (constant over timesteps) ----
    float P_B, cA, cB, dA, dB;
    {
        float Q = tD2D0 * tD2D1;                // pair product
        #pragma unroll
        for (int off = 1; off < 32; off <<= 1) {
            float q = __shfl_up_sync(FULL, Q, off);
            if (lane >= off) Q *= q;
        }
        float Qex = __shfl_up_sync(FULL, Q, 1); // P[2L]
        if (lane == 0) Qex = 1.0f;
        float P_A = Qex * tD2D0;                // P[2L+1]
        P_B = Q;                                // P[2L+2]
        cA = __fdividef(tM2D0, P_A);
        cB = __fdividef(tM2D1, P_B);
        dA = tD2M0 * Qex;
        dB = tD2M1 * P_A;
    }

    // ---- init linear-space states ----
    float FM0 = (lane == 0) ? 1.0f : 0.0f;
    float FM1 = 0.0f, FI0 = 0.0f, FI1 = 0.0f, FM64 = 0.0f, FI64 = 0.0f;
    float excl, inclA, T;
    float S = 0.0f;

    const float* eP = &sE[(warp * 4) * 32 + lane];

#define DCHAIN()                                                              \
    {                                                                         \
        float uA = cA * FM0;                                                  \
        float uB = cB * FM1;                                                  \
        float pr = uA + uB;                                                   \
        T = pr;                                                               \
        _Pragma("unroll")                                                     \
        for (int off = 1; off < 32; off <<= 1) {                              \
            float t = __shfl_up_sync(FULL, T, off);                           \
            if (lane >= off) T += t;                                          \
        }                                                                     \
        excl = T - pr;                                                        \
        inclA = excl + uA;                                                    \
    }

#define STEP(l)                                                               \
    {                                                                         \
        int x = sx[warp][(l)];                                                \
        const float* ep = eP + x * 32;                                        \
        float eA = ep[0];                                                     \
        float eB = ep[512];                                                   \
        float eC = ep[1024];                                                  \
        float p0 = fmaf(dA, excl, fmaf(tI2M0, FI0, tM2M0 * FM0));             \
        float p1 = fmaf(dB, inclA, fmaf(tI2M1, FI1, tM2M1 * FM1));            \
        float pUp = __shfl_up_sync(FULL, p1, 1);                              \
        FI0 = fmaf(tqI2I0, FI0, tqM2I0 * FM0);   /* uses OLD FM */            \
        FI1 = fmaf(tqI2I1, FI1, tqM2I1 * FM1);                                \
        FI64 = fmaf(tq64I2I, FI64, tq64M2I * FM64);                           \
        FM0 = eA * pUp;           /* lane0: eA==0 -> stays 0 */               \
        FM1 = eB * p0;                                                        \
        FM64 = eC * p1;           /* valid on lane 31 only */                 \
        DCHAIN();                                                             \
    }

    DCHAIN();  // from initial fM

    #pragma unroll 1
    for (int lq = 0; lq < 16; lq++) {
        STEP(8 * lq + 0);
        STEP(8 * lq + 1);
        STEP(8 * lq + 2);
        STEP(8 * lq + 3);
        STEP(8 * lq + 4);
        STEP(8 * lq + 5);
        STEP(8 * lq + 6);
        STEP(8 * lq + 7);
        // rescale by warp max of persistent states; scale scan outputs too
        float m = fmaxf(fmaxf(FM0, FM1), fmaxf(FI0, FI1));
        m = fmaxf(m, fmaxf(FM64, FI64));
        #pragma unroll
        for (int off = 16; off; off >>= 1)
            m = fmaxf(m, __shfl_xor_sync(FULL, m, off));
        m = fmaxf(m, 1e-30f);
        float r = 1.0f / m;
        S += __logf(m);
        FM0 *= r; FM1 *= r; FI0 *= r; FI1 *= r;
        FM64 *= r; FI64 *= r;
        excl *= r; inclA *= r; T *= r;
    }

    // ---- final: three end transitions (lane 31 holds k=64) ----
    float fdTop = P_B * T;                      // fD[64] on lane 31
    float Pfin = fmaf(t64D2M, fdTop, fmaf(t64I2M, FI64, t64M2M * FM64));
    float loss = -(S + __logf(Pfin));           // valid on lane 31

    // ---- KLD: lanes 0..15 each handle one latent dim ----
    float kt = 0.0f;
    if (lane < 16) {
        float mu = mus[b * 16 + lane];
        float lv = logvars[b * 16 + lane];
        kt = 1.0f + lv - mu * mu - __expf(lv);
    }
    #pragma unroll
    for (int off = 16; off; off >>= 1)
        kt += __shfl_xor_sync(FULL, kt, off);
    float kld = -0.5f * kt;

    // ---- block partial, then last-block deterministic global reduction ----
    if (lane == 31) sred[warp] = loss + kld;
    __syncthreads();
    if (threadIdx.x == 0) {
        float v = (sred[0] + sred[1]) + (sred[2] + sred[3]);
        g_partials[blockIdx.x] = v;
        __threadfence();
        unsigned t = atomicAdd(&g_cnt, 1u);
        sflag = (t == gridDim.x - 1) ? 1 : 0;
    }
    __syncthreads();
    if (sflag) {
        float s = 0.0f;
        #pragma unroll
        for (int i = 0; i < 8; i++)
            s += __ldcg(&g_partials[threadIdx.x + 128 * i]);
        s2[threadIdx.x] = s;
        __syncthreads();
        #pragma unroll
        for (int st = 64; st; st >>= 1) {
            if (threadIdx.x < st) s2[threadIdx.x] += s2[threadIdx.x + st];
            __syncthreads();
        }
        if (threadIdx.x == 0) {
            out[0] = s2[0] * (1.0f / 4096.0f);
            g_cnt = 0;  // self-reset for graph replay
        }
    }
#undef STEP
#undef DCHAIN
}

extern "C" void kernel_launch(void* const* d_in, const int* in_sizes, int n_in,
                              void* d_out, int out_size) {
    const int*   x  = (const int*)d_in[0];    // batch_input (B,128)
    const float* a  = (const float*)d_in[1];  // transition_probs (B,65,7)
    const float* e  = (const float*)d_in[2];  // emission_probs (B,64,4)
    const float* mu = (const float*)d_in[3];  // mus (B,16)
    const float* lv = (const float*)d_in[4];  // logvars (B,16)
    const int B = in_sizes[0] / 128;          // 4096
    phmm_kernel<<<B / 4, 128>>>(x, a, e, mu, lv, (float*)d_out);
}

// round 4
// speedup vs baseline: 1.3591x; 1.1022x over previous
#include <cuda_runtime.h>

#define FULL 0xFFFFFFFFu

// Per-block partials + completion counter (static device scratch).
__device__ float g_partials[512];
__device__ unsigned int g_cnt = 0;

// Two batch elements per warp (16-lane segments). Lane sl (0..15) of a segment
// owns states k = 4sl..4sl+3; state 64 carried redundantly (sl=15 valid).
// Linear-space scaled forward; D-chain via constant prefix products folded
// into consumers, 16-wide segmented additive scan (4 shfl stages).
__global__ void __launch_bounds__(128)
phmm_kernel(const int* __restrict__ xin,       // (B,128) int32 in [0,4)
            const float* __restrict__ trans,   // (B,65,7)
            const float* __restrict__ emis,    // (B,64,4)
            const float* __restrict__ mus,     // (B,16)
            const float* __restrict__ logvars, // (B,16)
            float* __restrict__ out)           // scalar
{
    const int lane = threadIdx.x & 31;
    const int sl   = lane & 15;            // lane within segment
    const int seg  = lane >> 4;            // 0/1: which batch of this warp
    const int warp = threadIdx.x >> 5;
    const int b = blockIdx.x * 8 + warp * 2 + seg;

    // Shared: emission float4 LUT [warp][sym][lane], e63 LUT, symbols, reduction.
    __shared__ float4 sE4[4 * 4 * 32];     // 8KB
    __shared__ float  sEC[4 * 4 * 32];     // 2KB
    __shared__ int    sx[8 * 132];         // per (warp,seg), stride 132 de-conflicts
    __shared__ float  sred[8];
    __shared__ int    sflag;
    __shared__ float  s2[128];

    int* sxw = &sx[(warp * 2 + seg) * 132];
    {
        const int* xb = xin + b * 128;
        #pragma unroll
        for (int i = 0; i < 8; i++) sxw[sl + 16 * i] = xb[sl + 16 * i];
    }

    // ---- transitions: rows 4sl..4sl+3 (order M2M,M2I,M2D,I2M,I2I,D2M,D2D) ----
    const float* ab = trans + b * 455;
    const float* a0 = ab + 28 * sl;
    float tM2M[4], tqM2I[4], tI2M[4], tqI2I[4], tM2D[4], tD2M[4], tD2D[4];
    #pragma unroll
    for (int j = 0; j < 4; j++) {
        tM2M[j]  = __expf(a0[7 * j + 0]);
        tqM2I[j] = 0.25f * __expf(a0[7 * j + 1]);   // LOG_Q folded
        tM2D[j]  = __expf(a0[7 * j + 2]);
        tI2M[j]  = __expf(a0[7 * j + 3]);
        tqI2I[j] = 0.25f * __expf(a0[7 * j + 4]);
        tD2M[j]  = __expf(a0[7 * j + 5]);
        tD2D[j]  = __expf(a0[7 * j + 6]);
    }
    const float* a64 = ab + 64 * 7;
    float t64M2M  = __expf(a64[0]);
    float tq64M2I = 0.25f * __expf(a64[1]);
    float t64I2M  = __expf(a64[3]);
    float tq64I2I = 0.25f * __expf(a64[4]);
    float t64D2M  = __expf(a64[5]);

    // ---- emission LUTs ----
    // FM_new[4sl+j] needs e[4sl+j-1]; lane's float4 = (e[4sl-1],e[4sl],e[4sl+1],e[4sl+2]).
    // sl=0's .x forced to 0 so FM[0] of state 0 stays 0. eC = e[63] (state 64).
    const float* eb = emis + b * 256;
    {
        #pragma unroll
        for (int x = 0; x < 4; x++) {
            float4 v;
            v.x = (sl == 0) ? 0.0f : __expf(eb[(4 * sl - 1) * 4 + x]);
            v.y = __expf(eb[(4 * sl + 0) * 4 + x]);
            v.z = __expf(eb[(4 * sl + 1) * 4 + x]);
            v.w = __expf(eb[(4 * sl + 2) * 4 + x]);
            sE4[(warp * 4 + x) * 32 + lane] = v;
            sEC[(warp * 4 + x) * 32 + lane] = __expf(eb[63 * 4 + x]);
        }
    }
    __syncwarp();   // each warp touches only its own LUT/sx rows

    // ---- prefix products of the D-chain coefficients (constant in time) ----
    // chain: fD[k] = tM2D[k-1]*fM[k-1] + tD2D[k-1]*fD[k-1]; P[k] = prod tD2D[<k].
    float cc[4], dd[4], P64fac;
    {
        float q0 = tD2D[0], q01 = q0 * tD2D[1], q012 = q01 * tD2D[2], q0123 = q012 * tD2D[3];
        float Q = q0123;
        #pragma unroll
        for (int off = 1; off < 16; off <<= 1) {
            float q = __shfl_up_sync(FULL, Q, off, 16);
            if (sl >= off) Q *= q;
        }
        float Pex = __shfl_up_sync(FULL, Q, 1, 16);   // P[4sl]
        if (sl == 0) Pex = 1.0f;
        float Pa = Pex * q0, Pb = Pex * q01, Pc = Pex * q012, Pd = Pex * q0123;
        dd[0] = tD2M[0] * Pex;  // tD2M[4sl+j]*P[4sl+j]
        dd[1] = tD2M[1] * Pa;
        dd[2] = tD2M[2] * Pb;
        dd[3] = tD2M[3] * Pc;
        cc[0] = __fdividef(tM2D[0], Pa);  // tM2D[4sl+j]/P[4sl+j+1]
        cc[1] = __fdividef(tM2D[1], Pb);
        cc[2] = __fdividef(tM2D[2], Pc);
        cc[3] = __fdividef(tM2D[3], Pd);
        P64fac = Pd;                       // on sl=15: P[64]
    }

    // ---- init states ----
    float FM[4] = {(sl == 0) ? 1.0f : 0.0f, 0.0f, 0.0f, 0.0f};
    float FI[4] = {0.0f, 0.0f, 0.0f, 0.0f};
    float FM64 = 0.0f, FI64 = 0.0f;
    float w0, w1, w2, w3, incl;
    float S = 0.0f;

    const float4* sE4w = &sE4[warp * 128 + lane];
    const float*  sECw = &sEC[warp * 128 + lane];

    // fD[4sl+j] = P[4sl+j]*(segment-exclusive-prefix + local prefix) -> w_j raw sums.
#define DCHAIN()                                                              \
    {                                                                         \
        float u0 = cc[0] * FM[0], u1 = cc[1] * FM[1];                         \
        float u2 = cc[2] * FM[2], u3 = cc[3] * FM[3];                         \
        float s0 = u0, s1 = s0 + u1, s2 = s1 + u2, s3 = s2 + u3;              \
        float T = s3;                                                         \
        _Pragma("unroll")                                                     \
        for (int off = 1; off < 16; off <<= 1) {                              \
            float t = __shfl_up_sync(FULL, T, off, 16);                       \
            if (sl >= off) T += t;                                            \
        }                                                                     \
        incl = T;                                                             \
        float ex = T - s3;                                                    \
        w0 = ex; w1 = ex + s0; w2 = ex + s1; w3 = ex + s2;                    \
    }

#define STEP(l)                                                               \
    {                                                                         \
        int x = sxw[(l)];                                                     \
        float4 ev = sE4w[x * 32];                                             \
        float  eC = sECw[x * 32];                                             \
        float p0 = fmaf(dd[0], w0, fmaf(tI2M[0], FI[0], tM2M[0] * FM[0]));    \
        float p1 = fmaf(dd[1], w1, fmaf(tI2M[1], FI[1], tM2M[1] * FM[1]));    \
        float p2 = fmaf(dd[2], w2, fmaf(tI2M[2], FI[2], tM2M[2] * FM[2]));    \
        float p3 = fmaf(dd[3], w3, fmaf(tI2M[3], FI[3], tM2M[3] * FM[3]));    \
        float pUp = __shfl_up_sync(FULL, p3, 1, 16);                          \
        FI[0] = fmaf(tqI2I[0], FI[0], tqM2I[0] * FM[0]);  /* OLD FM */        \
        FI[1] = fmaf(tqI2I[1], FI[1], tqM2I[1] * FM[1]);                      \
        FI[2] = fmaf(tqI2I[2], FI[2], tqM2I[2] * FM[2]);                      \
        FI[3] = fmaf(tqI2I[3], FI[3], tqM2I[3] * FM[3]);                      \
        FI64  = fmaf(tq64I2I, FI64, tq64M2I * FM64);                          \
        FM[0] = ev.x * pUp;        /* sl=0: ev.x==0 keeps state0 at 0 */      \
        FM[1] = ev.y * p0;                                                    \
        FM[2] = ev.z * p1;                                                    \
        FM[3] = ev.w * p2;                                                    \
        FM64  = eC * p3;           /* valid on sl=15 only */                  \
        DCHAIN();                                                             \
    }

    DCHAIN();  // from initial fM

    #pragma unroll 1
    for (int lq = 0; lq < 16; lq++) {
        STEP(8 * lq + 0);
        STEP(8 * lq + 1);
        STEP(8 * lq + 2);
        STEP(8 * lq + 3);
        STEP(8 * lq + 4);
        STEP(8 * lq + 5);
        STEP(8 * lq + 6);
        STEP(8 * lq + 7);
        // rescale by segment max; scale scan outputs too (consumed next step)
        float m = fmaxf(fmaxf(FM[0], FM[1]), fmaxf(FM[2], FM[3]));
        m = fmaxf(m, fmaxf(fmaxf(FI[0], FI[1]), fmaxf(FI[2], FI[3])));
        m = fmaxf(m, fmaxf(FM64, FI64));
        #pragma unroll
        for (int off = 1; off < 16; off <<= 1)
            m = fmaxf(m, __shfl_xor_sync(FULL, m, off, 16));
        m = fmaxf(m, 1e-30f);
        float r = 1.0f / m;
        S += __logf(m);
        FM[0] *= r; FM[1] *= r; FM[2] *= r; FM[3] *= r;
        FI[0] *= r; FI[1] *= r; FI[2] *= r; FI[3] *= r;
        FM64 *= r; FI64 *= r;
        w0 *= r; w1 *= r; w2 *= r; w3 *= r; incl *= r;
    }

    // ---- final: three end transitions (sl=15 holds state 64 & full prefix) ----
    float fdTop = P64fac * incl;                  // fD[64] on sl=15
    float Pfin = fmaf(t64D2M, fdTop, fmaf(t64I2M, FI64, t64M2M * FM64));
    float loss = -(S + __logf(Pfin));             // valid on sl=15

    // ---- KLD: all 16 segment lanes, one latent dim each ----
    float kt;
    {
        float mu = mus[b * 16 + sl];
        float lv = logvars[b * 16 + sl];
        kt = 1.0f + lv - mu * mu - __expf(lv);
    }
    #pragma unroll
    for (int off = 1; off < 16; off <<= 1)
        kt += __shfl_xor_sync(FULL, kt, off, 16);

    if (sl == 15) sred[warp * 2 + seg] = loss - 0.5f * kt;
    __syncthreads();
    if (threadIdx.x == 0) {
        float v = ((sred[0] + sred[1]) + (sred[2] + sred[3]))
                + ((sred[4] + sred[5]) + (sred[6] + sred[7]));
        g_partials[blockIdx.x] = v;
        __threadfence();
        unsigned t = atomicAdd(&g_cnt, 1u);
        sflag = (t == gridDim.x - 1) ? 1 : 0;
    }
    __syncthreads();
    if (sflag) {
        float s = 0.0f;
        #pragma unroll
        for (int i = 0; i < 4; i++)
            s += __ldcg(&g_partials[threadIdx.x + 128 * i]);
        s2[threadIdx.x] = s;
        __syncthreads();
        #pragma unroll
        for (int st = 64; st; st >>= 1) {
            if (threadIdx.x < st) s2[threadIdx.x] += s2[threadIdx.x + st];
            __syncthreads();
        }
        if (threadIdx.x == 0) {
            out[0] = s2[0] * (1.0f / 4096.0f);
            g_cnt = 0;  // self-reset for graph replay
        }
    }
#undef STEP
#undef DCHAIN
}

extern "C" void kernel_launch(void* const* d_in, const int* in_sizes, int n_in,
                              void* d_out, int out_size) {
    const int*   x  = (const int*)d_in[0];    // batch_input (B,128)
    const float* a  = (const float*)d_in[1];  // transition_probs (B,65,7)
    const float* e  = (const float*)d_in[2];  // emission_probs (B,64,4)
    const float* mu = (const float*)d_in[3];  // mus (B,16)
    const float* lv = (const float*)d_in[4];  // logvars (B,16)
    const int B = in_sizes[0] / 128;          // 4096
    phmm_kernel<<<B / 8, 128>>>(x, a, e, mu, lv, (float*)d_out);
}

// round 5
// speedup vs baseline: 1.3883x; 1.0215x over previous
#include <cuda_runtime.h>

#define FULL 0xFFFFFFFFu
typedef unsigned long long u64;

// Per-block partials + completion counter (static device scratch).
__device__ float g_partials[512];
__device__ unsigned int g_cnt = 0;

// ---- f32x2 packed helpers (sm_100+ PTX) ----
__device__ __forceinline__ u64 pk(float lo, float hi) {
    u64 d; asm("mov.b64 %0, {%1, %2};" : "=l"(d) : "f"(lo), "f"(hi)); return d;
}
__device__ __forceinline__ float lo2(u64 d) { return __uint_as_float((unsigned)d); }
__device__ __forceinline__ float hi2(u64 d) { return __uint_as_float((unsigned)(d >> 32)); }
__device__ __forceinline__ u64 fma2(u64 a, u64 b, u64 c) {
    u64 d; asm("fma.rn.f32x2 %0, %1, %2, %3;" : "=l"(d) : "l"(a), "l"(b), "l"(c)); return d;
}
__device__ __forceinline__ u64 mul2(u64 a, u64 b) {
    u64 d; asm("mul.rn.f32x2 %0, %1, %2;" : "=l"(d) : "l"(a), "l"(b)); return d;
}
__device__ __forceinline__ u64 add2(u64 a, u64 b) {
    u64 d; asm("add.rn.f32x2 %0, %1, %2;" : "=l"(d) : "l"(a), "l"(b)); return d;
}

// Two batch elements per warp (16-lane segments), 4 states/lane packed in two
// f32x2 pairs. Linear-space scaled forward; D-chain via constant prefix
// products folded into consumers; 16-wide segmented additive scan (4 stages).
__global__ void __launch_bounds__(128)
phmm_kernel(const int* __restrict__ xin,       // (B,128) int32 in [0,4)
            const float* __restrict__ trans,   // (B,65,7)
            const float* __restrict__ emis,    // (B,64,4)
            const float* __restrict__ mus,     // (B,16)
            const float* __restrict__ logvars, // (B,16)
            float* __restrict__ out)           // scalar
{
    const int lane = threadIdx.x & 31;
    const int sl   = lane & 15;            // lane within segment
    const int seg  = lane >> 4;            // which batch of this warp
    const int warp = threadIdx.x >> 5;
    const int b = blockIdx.x * 8 + warp * 2 + seg;

    __shared__ float4 sE4[4 * 4 * 32];     // [warp][sym][lane] emission quads
    __shared__ float  sEC[4 * 4 * 32];     // e[63] replicated
    __shared__ int    sx[8 * 132];         // symbols, stride de-conflicts
    __shared__ float  sred[8];
    __shared__ int    sflag;
    __shared__ float  s2[128];

    int* sxw = &sx[(warp * 2 + seg) * 132];
    {
        const int* xb = xin + b * 128;
        #pragma unroll
        for (int i = 0; i < 8; i++) sxw[sl + 16 * i] = xb[sl + 16 * i];
    }

    // ---- transitions (order M2M,M2I,M2D,I2M,I2I,D2M,D2D), rows 4sl..4sl+3 ----
    const float* ab = trans + b * 455;
    const float* a0 = ab + 28 * sl;
    float tM2M[4], tqM2I[4], tI2M[4], tqI2I[4], tM2D[4], tD2M[4], tD2D[4];
    #pragma unroll
    for (int j = 0; j < 4; j++) {
        tM2M[j]  = __expf(a0[7 * j + 0]);
        tqM2I[j] = 0.25f * __expf(a0[7 * j + 1]);   // LOG_Q folded
        tM2D[j]  = __expf(a0[7 * j + 2]);
        tI2M[j]  = __expf(a0[7 * j + 3]);
        tqI2I[j] = 0.25f * __expf(a0[7 * j + 4]);
        tD2M[j]  = __expf(a0[7 * j + 5]);
        tD2D[j]  = __expf(a0[7 * j + 6]);
    }
    const float* a64 = ab + 64 * 7;
    float t64M2M  = __expf(a64[0]);
    float tq64M2I = 0.25f * __expf(a64[1]);
    float t64I2M  = __expf(a64[3]);
    float tq64I2I = 0.25f * __expf(a64[4]);
    float t64D2M  = __expf(a64[5]);

    // ---- emission LUTs ----
    const float* eb = emis + b * 256;
    {
        #pragma unroll
        for (int x = 0; x < 4; x++) {
            float4 v;
            v.x = (sl == 0) ? 0.0f : __expf(eb[(4 * sl - 1) * 4 + x]);
            v.y = __expf(eb[(4 * sl + 0) * 4 + x]);
            v.z = __expf(eb[(4 * sl + 1) * 4 + x]);
            v.w = __expf(eb[(4 * sl + 2) * 4 + x]);
            sE4[(warp * 4 + x) * 32 + lane] = v;
            sEC[(warp * 4 + x) * 32 + lane] = __expf(eb[63 * 4 + x]);
        }
    }
    __syncwarp();

    // ---- prefix products of D-chain coefficients (constant in time) ----
    float P64fac;
    u64 cc01, cc23, dd01, dd23;
    {
        float q0 = tD2D[0], q01 = q0 * tD2D[1], q012 = q01 * tD2D[2], q0123 = q012 * tD2D[3];
        float Q = q0123;
        #pragma unroll
        for (int off = 1; off < 16; off <<= 1) {
            float q = __shfl_up_sync(FULL, Q, off, 16);
            if (sl >= off) Q *= q;
        }
        float Pex = __shfl_up_sync(FULL, Q, 1, 16);   // P[4sl]
        if (sl == 0) Pex = 1.0f;
        float Pa = Pex * q0, Pb = Pex * q01, Pc = Pex * q012, Pd = Pex * q0123;
        dd01 = pk(tD2M[0] * Pex, tD2M[1] * Pa);
        dd23 = pk(tD2M[2] * Pb,  tD2M[3] * Pc);
        cc01 = pk(__fdividef(tM2D[0], Pa), __fdividef(tM2D[1], Pb));
        cc23 = pk(__fdividef(tM2D[2], Pc), __fdividef(tM2D[3], Pd));
        P64fac = Pd;                        // on sl=15: P[64]
    }
    const u64 tM2M01  = pk(tM2M[0], tM2M[1]),   tM2M23  = pk(tM2M[2], tM2M[3]);
    const u64 tI2M01  = pk(tI2M[0], tI2M[1]),   tI2M23  = pk(tI2M[2], tI2M[3]);
    const u64 tqI2I01 = pk(tqI2I[0], tqI2I[1]), tqI2I23 = pk(tqI2I[2], tqI2I[3]);
    const u64 tqM2I01 = pk(tqM2I[0], tqM2I[1]), tqM2I23 = pk(tqM2I[2], tqM2I[3]);

    // ---- init states ----
    u64 FM01 = pk((sl == 0) ? 1.0f : 0.0f, 0.0f), FM23 = pk(0.0f, 0.0f);
    u64 FI01 = pk(0.0f, 0.0f), FI23 = pk(0.0f, 0.0f);
    float FM64 = 0.0f, FI64 = 0.0f;
    u64 w01, w23;
    float incl, S = 0.0f;

    unsigned sE4a = (unsigned)__cvta_generic_to_shared(&sE4[warp * 128 + lane]);
    const float* sECw = &sEC[warp * 128 + lane];

#define DCHAIN()                                                              \
    {                                                                         \
        u64 u01 = mul2(cc01, FM01);                                           \
        u64 u23 = mul2(cc23, FM23);                                           \
        float u0 = lo2(u01), u1 = hi2(u01), u2 = lo2(u23), u3 = hi2(u23);     \
        float s1 = u0 + u1, s2 = s1 + u2, s3 = s2 + u3;                       \
        float T = s3;                                                         \
        _Pragma("unroll")                                                     \
        for (int off = 1; off < 16; off <<= 1) {                              \
            float t = __shfl_up_sync(FULL, T, off, 16);                       \
            if (sl >= off) T += t;                                            \
        }                                                                     \
        incl = T;                                                             \
        float ex = T - s3;                                                    \
        w01 = pk(ex, ex + u0);                                                \
        w23 = pk(ex + s1, ex + s2);                                           \
    }

#define STEP(x)                                                               \
    {                                                                         \
        u64 ev01, ev23;                                                       \
        asm("ld.shared.v2.u64 {%0, %1}, [%2];"                                \
            : "=l"(ev01), "=l"(ev23) : "r"(sE4a + (unsigned)(x) * 512));      \
        float eC = sECw[(x) * 32];                                            \
        u64 p01 = fma2(dd01, w01, fma2(tI2M01, FI01, mul2(tM2M01, FM01)));    \
        u64 p23 = fma2(dd23, w23, fma2(tI2M23, FI23, mul2(tM2M23, FM23)));    \
        float p3 = hi2(p23);                                                  \
        float pUp = __shfl_up_sync(FULL, p3, 1, 16);                          \
        FI01 = fma2(tqI2I01, FI01, mul2(tqM2I01, FM01));  /* OLD FM */        \
        FI23 = fma2(tqI2I23, FI23, mul2(tqM2I23, FM23));                      \
        FI64 = fmaf(tq64I2I, FI64, tq64M2I * FM64);                           \
        FM01 = mul2(ev01, pk(pUp, lo2(p01)));  /* sl0: ev.x==0 */             \
        FM23 = mul2(ev23, pk(hi2(p01), lo2(p23)));                            \
        FM64 = eC * p3;                        /* valid on sl=15 */           \
        DCHAIN();                                                             \
    }

    DCHAIN();  // from initial fM

    #pragma unroll 1
    for (int lq = 0; lq < 16; lq++) {
        int4 xa = *(const int4*)&sxw[8 * lq];
        int4 xb4 = *(const int4*)&sxw[8 * lq + 4];
        STEP(xa.x); STEP(xa.y); STEP(xa.z); STEP(xa.w);
        STEP(xb4.x); STEP(xb4.y); STEP(xb4.z); STEP(xb4.w);
        // rescale by segment max (pair halves are plain regs at SASS level)
        float m = fmaxf(fmaxf(lo2(FM01), hi2(FM01)), fmaxf(lo2(FM23), hi2(FM23)));
        m = fmaxf(m, fmaxf(fmaxf(lo2(FI01), hi2(FI01)), fmaxf(lo2(FI23), hi2(FI23))));
        m = fmaxf(m, fmaxf(FM64, FI64));
        #pragma unroll
        for (int off = 1; off < 16; off <<= 1)
            m = fmaxf(m, __shfl_xor_sync(FULL, m, off, 16));
        m = fmaxf(m, 1e-30f);
        float r = 1.0f / m;
        S += __logf(m);
        u64 rr = pk(r, r);
        FM01 = mul2(FM01, rr); FM23 = mul2(FM23, rr);
        FI01 = mul2(FI01, rr); FI23 = mul2(FI23, rr);
        w01 = mul2(w01, rr);   w23 = mul2(w23, rr);
        FM64 *= r; FI64 *= r; incl *= r;
    }

    // ---- final: three end transitions (sl=15 holds state 64 & full prefix) ----
    float fdTop = P64fac * incl;
    float Pfin = fmaf(t64D2M, fdTop, fmaf(t64I2M, FI64, t64M2M * FM64));
    float loss = -(S + __logf(Pfin));             // valid on sl=15

    // ---- KLD: 16 segment lanes, one latent dim each ----
    float kt;
    {
        float mu = mus[b * 16 + sl];
        float lv = logvars[b * 16 + sl];
        kt = 1.0f + lv - mu * mu - __expf(lv);
    }
    #pragma unroll
    for (int off = 1; off < 16; off <<= 1)
        kt += __shfl_xor_sync(FULL, kt, off, 16);

    if (sl == 15) sred[warp * 2 + seg] = loss - 0.5f * kt;
    __syncthreads();
    if (threadIdx.x == 0) {
        float v = ((sred[0] + sred[1]) + (sred[2] + sred[3]))
                + ((sred[4] + sred[5]) + (sred[6] + sred[7]));
        g_partials[blockIdx.x] = v;
        __threadfence();
        unsigned t = atomicAdd(&g_cnt, 1u);
        sflag = (t == gridDim.x - 1) ? 1 : 0;
    }
    __syncthreads();
    if (sflag) {
        float s = 0.0f;
        #pragma unroll
        for (int i = 0; i < 4; i++)
            s += __ldcg(&g_partials[threadIdx.x + 128 * i]);
        s2[threadIdx.x] = s;
        __syncthreads();
        #pragma unroll
        for (int st = 64; st; st >>= 1) {
            if (threadIdx.x < st) s2[threadIdx.x] += s2[threadIdx.x + st];
            __syncthreads();
        }
        if (threadIdx.x == 0) {
            out[0] = s2[0] * (1.0f / 4096.0f);
            g_cnt = 0;  // self-reset for graph replay
        }
    }
#undef STEP
#undef DCHAIN
}

extern "C" void kernel_launch(void* const* d_in, const int* in_sizes, int n_in,
                              void* d_out, int out_size) {
    const int*   x  = (const int*)d_in[0];    // batch_input (B,128)
    const float* a  = (const float*)d_in[1];  // transition_probs (B,65,7)
    const float* e  = (const float*)d_in[2];  // emission_probs (B,64,4)
    const float* mu = (const float*)d_in[3];  // mus (B,16)
    const float* lv = (const float*)d_in[4];  // logvars (B,16)
    const int B = in_sizes[0] / 128;          // 4096
    phmm_kernel<<<B / 8, 128>>>(x, a, e, mu, lv, (float*)d_out);
}